// round 1
// baseline (speedup 1.0000x reference)
#include <cuda_runtime.h>
#include <cstdint>

// Problem constants (fixed shapes per reference)
#define N_NODES 50000
#define N_EDGES 640000
#define R_REL   8
#define F_IN    128   // K of both GEMMs
#define F_HID   128
#define F_OUT   64

// Scratch (device globals: allocation-free per harness rules)
__device__ float g_Wcat[128 * 1152];                       // packed [K, (R+1)*Fout], reused per layer
__device__ float g_Y[(long long)N_NODES * 1152];           // GEMM output, reused per layer
__device__ float g_h1[(long long)N_NODES * F_HID];         // layer-1 pre-ReLU output
__device__ float g_h2[(long long)N_NODES * F_OUT];         // layer-2 pre-ReLU output
__device__ int   g_cnt[R_REL * N_NODES];                   // per-(relation,dst) edge counts
__device__ float g_w[N_EDGES];                             // per-edge weight 1/max(cnt,1)

// ---------------------------------------------------------------------------
__global__ void zero_cnt_kernel() {
    int i = blockIdx.x * blockDim.x + threadIdx.x;
    if (i < R_REL * N_NODES) g_cnt[i] = 0;
}

__global__ void count_kernel(const int* __restrict__ etype, const int* __restrict__ dst) {
    int e = blockIdx.x * blockDim.x + threadIdx.x;
    if (e < N_EDGES) atomicAdd(&g_cnt[etype[e] * N_NODES + dst[e]], 1);
}

__global__ void weight_kernel(const int* __restrict__ etype, const int* __restrict__ dst) {
    int e = blockIdx.x * blockDim.x + threadIdx.x;
    if (e < N_EDGES) {
        int c = g_cnt[etype[e] * N_NODES + dst[e]];
        g_w[e] = 1.0f / (float)(c > 0 ? c : 1);
    }
}

// Pack W [R, 128, Fout] and root [128, Fout] into Wcat [128, (R+1)*Fout] row-major.
__global__ void repack_kernel(const float* __restrict__ W, const float* __restrict__ root, int Fout) {
    int Nw = (R_REL + 1) * Fout;
    int idx = blockIdx.x * blockDim.x + threadIdx.x;
    if (idx >= 128 * Nw) return;
    int k = idx / Nw, j = idx % Nw;
    float v;
    if (j < R_REL * Fout) {
        int r = j / Fout, o = j % Fout;
        v = W[((long long)r * 128 + k) * Fout + o];
    } else {
        v = root[k * Fout + (j - R_REL * Fout)];
    }
    g_Wcat[idx] = v;
}

// ---------------------------------------------------------------------------
// SGEMM: C[M, Nw] = act(A[M,128]) @ B[128, Nw].  BM=BN=64, BK=16, 256 thr, 4x4/thr.
template <bool RELU_A>
__global__ __launch_bounds__(256)
void gemm_kernel(const float* __restrict__ A, float* __restrict__ C, int M, int Nw) {
    const float* __restrict__ B = g_Wcat;
    __shared__ float As[16][64];
    __shared__ float Bs[16][64];

    int tid = threadIdx.x;
    int tx = tid & 15;          // n-tile index
    int ty = tid >> 4;          // m-tile index
    int bm = blockIdx.y * 64;
    int bn = blockIdx.x * 64;

    int arow = tid >> 2;        // 0..63
    int akq  = tid & 3;         // which float4 within 16 K values
    int brow = tid >> 4;        // 0..15
    int bnq  = tid & 15;        // which float4 within 64 N values

    float acc[4][4] = {};

    for (int k0 = 0; k0 < 128; k0 += 16) {
        float4 av = make_float4(0.f, 0.f, 0.f, 0.f);
        int gm = bm + arow;
        if (gm < M) av = *(const float4*)(A + (long long)gm * 128 + k0 + akq * 4);
        if (RELU_A) {
            av.x = fmaxf(av.x, 0.f); av.y = fmaxf(av.y, 0.f);
            av.z = fmaxf(av.z, 0.f); av.w = fmaxf(av.w, 0.f);
        }
        As[akq * 4 + 0][arow] = av.x;
        As[akq * 4 + 1][arow] = av.y;
        As[akq * 4 + 2][arow] = av.z;
        As[akq * 4 + 3][arow] = av.w;

        float4 bv = *(const float4*)(B + (long long)(k0 + brow) * Nw + bn + bnq * 4);
        *(float4*)&Bs[brow][bnq * 4] = bv;

        __syncthreads();

#pragma unroll
        for (int kk = 0; kk < 16; kk++) {
            float a[4], b[4];
            *(float4*)a = *(const float4*)&As[kk][ty * 4];
            *(float4*)b = *(const float4*)&Bs[kk][tx * 4];
#pragma unroll
            for (int i = 0; i < 4; i++)
#pragma unroll
                for (int j = 0; j < 4; j++)
                    acc[i][j] += a[i] * b[j];
        }
        __syncthreads();
    }

#pragma unroll
    for (int i = 0; i < 4; i++) {
        int gm = bm + ty * 4 + i;
        if (gm < M) {
            float4 r = make_float4(acc[i][0], acc[i][1], acc[i][2], acc[i][3]);
            *(float4*)(C + (long long)gm * Nw + bn + tx * 4) = r;
        }
    }
}

// ---------------------------------------------------------------------------
// h[n][o] = Y[n][R*Fout + o] + b[o]   (root-term + bias init before scatter)
__global__ void init_h_kernel(const float* __restrict__ b, float* __restrict__ h,
                              int Fout, int stride) {
    long long i = (long long)blockIdx.x * blockDim.x + threadIdx.x;
    long long total = (long long)N_NODES * Fout;
    if (i < total) {
        int n = (int)(i / Fout), o = (int)(i % Fout);
        h[i] = g_Y[(long long)n * stride + R_REL * Fout + o] + b[o];
    }
}

// One warp per edge; Fout=128: each lane does one float4 red into h[dst].
__global__ __launch_bounds__(256)
void scatter128_kernel(const int* __restrict__ src, const int* __restrict__ dst,
                       const int* __restrict__ etype, float* __restrict__ h) {
    int e = (int)(((long long)blockIdx.x * blockDim.x + threadIdx.x) >> 5);
    int lane = threadIdx.x & 31;
    if (e >= N_EDGES) return;
    int s = src[e], d = dst[e], t = etype[e];
    float wt = g_w[e];
    float4 v = *(const float4*)(g_Y + (long long)s * 1152 + t * 128 + lane * 4);
    v.x *= wt; v.y *= wt; v.z *= wt; v.w *= wt;
    float* out = h + (long long)d * 128 + lane * 4;
    asm volatile("red.global.add.v4.f32 [%0], {%1, %2, %3, %4};"
                 :: "l"(out), "f"(v.x), "f"(v.y), "f"(v.z), "f"(v.w) : "memory");
}

// One warp per edge; Fout=64: each lane does one float2 red into h[dst].
__global__ __launch_bounds__(256)
void scatter64_kernel(const int* __restrict__ src, const int* __restrict__ dst,
                      const int* __restrict__ etype, float* __restrict__ h) {
    int e = (int)(((long long)blockIdx.x * blockDim.x + threadIdx.x) >> 5);
    int lane = threadIdx.x & 31;
    if (e >= N_EDGES) return;
    int s = src[e], d = dst[e], t = etype[e];
    float wt = g_w[e];
    float2 v = *(const float2*)(g_Y + (long long)s * 576 + t * 64 + lane * 2);
    v.x *= wt; v.y *= wt;
    float* out = h + (long long)d * 64 + lane * 2;
    asm volatile("red.global.add.v2.f32 [%0], {%1, %2};"
                 :: "l"(out), "f"(v.x), "f"(v.y) : "memory");
}

// logits[n][c] = bc[c] + sum_o relu(h2[n][o]) * Wc[o][c], warp per node.
__global__ __launch_bounds__(256)
void classifier_kernel(const float* __restrict__ Wc, const float* __restrict__ bc,
                       float* __restrict__ out) {
    int n = (int)(((long long)blockIdx.x * blockDim.x + threadIdx.x) >> 5);
    int lane = threadIdx.x & 31;
    if (n >= N_NODES) return;
    float a0 = 0.f, a1 = 0.f;
#pragma unroll
    for (int o = lane; o < 64; o += 32) {
        float v = fmaxf(g_h2[(long long)n * 64 + o], 0.f);
        a0 += v * Wc[o * 2 + 0];
        a1 += v * Wc[o * 2 + 1];
    }
#pragma unroll
    for (int off = 16; off; off >>= 1) {
        a0 += __shfl_down_sync(0xffffffffu, a0, off);
        a1 += __shfl_down_sync(0xffffffffu, a1, off);
    }
    if (lane == 0) {
        out[n * 2 + 0] = a0 + bc[0];
        out[n * 2 + 1] = a1 + bc[1];
    }
}

// ---------------------------------------------------------------------------
extern "C" void kernel_launch(void* const* d_in, const int* in_sizes, int n_in,
                              void* d_out, int out_size) {
    const float* x     = (const float*)d_in[0];
    const int*   eidx  = (const int*)d_in[1];
    const int*   etype = (const int*)d_in[2];
    const float* W1    = (const float*)d_in[3];
    const float* root1 = (const float*)d_in[4];
    const float* b1    = (const float*)d_in[5];
    const float* W2    = (const float*)d_in[6];
    const float* root2 = (const float*)d_in[7];
    const float* b2    = (const float*)d_in[8];
    const float* Wc    = (const float*)d_in[9];
    const float* bc    = (const float*)d_in[10];
    float* logits = (float*)d_out;

    const int* src = eidx;
    const int* dst = eidx + N_EDGES;

    // Get raw pointers to scratch symbols for kernels needing them as args
    // (kernels reference globals directly; only h buffers passed by symbol use)
    // -- all kernels reference __device__ globals directly, no symbol lookups.

    // Edge-structure preprocessing (shared by both layers)
    zero_cnt_kernel<<<(R_REL * N_NODES + 255) / 256, 256>>>();
    count_kernel<<<(N_EDGES + 255) / 256, 256>>>(etype, dst);
    weight_kernel<<<(N_EDGES + 255) / 256, 256>>>(etype, dst);

    float* h1p; cudaGetSymbolAddress((void**)&h1p, g_h1);
    float* h2p; cudaGetSymbolAddress((void**)&h2p, g_h2);
    float* Yp;  cudaGetSymbolAddress((void**)&Yp, g_Y);

    // ---- Layer 1: Fout=128, Nw=1152 ----
    {
        const int Fout = F_HID, Nw = (R_REL + 1) * Fout;  // 1152
        repack_kernel<<<(128 * Nw + 255) / 256, 256>>>(W1, root1, Fout);
        dim3 grid(Nw / 64, (N_NODES + 63) / 64);
        gemm_kernel<false><<<grid, 256>>>(x, Yp, N_NODES, Nw);
        init_h_kernel<<<((long long)N_NODES * Fout + 255) / 256, 256>>>(b1, h1p, Fout, Nw);
        scatter128_kernel<<<(N_EDGES * 32 + 255) / 256, 256>>>(src, dst, etype, h1p);
    }

    // ---- Layer 2: Fout=64, Nw=576 (A = relu(h1)) ----
    {
        const int Fout = F_OUT, Nw = (R_REL + 1) * Fout;  // 576
        repack_kernel<<<(128 * Nw + 255) / 256, 256>>>(W2, root2, Fout);
        dim3 grid(Nw / 64, (N_NODES + 63) / 64);
        gemm_kernel<true><<<grid, 256>>>(h1p, Yp, N_NODES, Nw);
        init_h_kernel<<<((long long)N_NODES * Fout + 255) / 256, 256>>>(b2, h2p, Fout, Nw);
        scatter64_kernel<<<(N_EDGES * 32 + 255) / 256, 256>>>(src, dst, etype, h2p);
    }

    // ---- Classifier ----
    classifier_kernel<<<(N_NODES * 32 + 255) / 256, 256>>>(Wc, bc, logits);
}

// round 3
// speedup vs baseline: 1.5245x; 1.5245x over previous
#include <cuda_runtime.h>
#include <cuda_bf16.h>
#include <cstdint>

// Problem constants
#define N_NODES 50000
#define N_EDGES 640000
#define R_REL   8
#define F_HID   128
#define F_OUT   64
#define NW1     1152          // (R+1)*128
#define NW2     640           // (R+1)*64 = 576, padded to 640
#define KTOT    384           // 3 * 128 (split-bf16 concat K)

// GEMM tile config
#define BM 128
#define BN 128
#define BK 64

// ---------------------------------------------------------------------------
// Device scratch (allocation-free)
__device__ float         g_Y[(long long)N_NODES * NW1];
__device__ float         g_h1[(long long)N_NODES * F_HID];
__device__ float         g_h2[(long long)N_NODES * F_OUT];
__device__ int           g_cnt[R_REL * N_NODES];
__device__ float         g_w[N_EDGES];
__device__ __nv_bfloat16 g_A[(long long)N_NODES * KTOT];   // [M][384] = [Ah|Al|Ah]
__device__ __nv_bfloat16 g_B1[NW1 * KTOT];                 // [Nw][384] = [Bh|Bh|Bl] (n-major)
__device__ __nv_bfloat16 g_B2[NW2 * KTOT];

__device__ __forceinline__ uint32_t smem_u32(const void* p) {
    uint32_t a;
    asm("{ .reg .u64 t; cvta.to.shared.u64 t, %1; cvt.u32.u64 %0, t; }" : "=r"(a) : "l"(p));
    return a;
}

// ---------------------------------------------------------------------------
// Edge preprocessing
__global__ void zero_cnt_kernel() {
    int i = blockIdx.x * blockDim.x + threadIdx.x;
    if (i < R_REL * N_NODES) g_cnt[i] = 0;
}
__global__ void count_kernel(const int* __restrict__ etype, const int* __restrict__ dst) {
    int e = blockIdx.x * blockDim.x + threadIdx.x;
    if (e < N_EDGES) atomicAdd(&g_cnt[etype[e] * N_NODES + dst[e]], 1);
}
__global__ void weight_kernel(const int* __restrict__ etype, const int* __restrict__ dst) {
    int e = blockIdx.x * blockDim.x + threadIdx.x;
    if (e < N_EDGES) {
        int c = g_cnt[etype[e] * N_NODES + dst[e]];
        g_w[e] = 1.0f / (float)(c > 0 ? c : 1);
    }
}

// ---------------------------------------------------------------------------
// A' build: row n gets [Ah(128) | Al(128) | Ah(128)] bf16. RELU optional.
template <bool RELU>
__global__ void convert_a_kernel(const float* __restrict__ A) {
    long long i = (long long)blockIdx.x * blockDim.x + threadIdx.x;
    if (i >= (long long)N_NODES * 128) return;
    int n = (int)(i >> 7), j = (int)(i & 127);
    float v = A[i];
    if (RELU) v = fmaxf(v, 0.f);
    __nv_bfloat16 h = __float2bfloat16(v);
    __nv_bfloat16 l = __float2bfloat16(v - __bfloat162float(h));
    __nv_bfloat16* row = g_A + (long long)n * KTOT;
    row[j] = h; row[128 + j] = l; row[256 + j] = h;
}

// B' build: row n (= r*Fout+o, or root block), col layout [Bh|Bh|Bl].
// Rows >= Nw_real are zero padding.
__global__ void convert_w_kernel(const float* __restrict__ W, const float* __restrict__ root,
                                 __nv_bfloat16* __restrict__ Bout,
                                 int Fout, int Nw_real, int Nw_pad) {
    int idx = blockIdx.x * blockDim.x + threadIdx.x;
    if (idx >= Nw_pad * 128) return;
    int n = idx >> 7, k = idx & 127;
    float v = 0.f;
    if (n < R_REL * Fout) {
        int r = n / Fout, o = n % Fout;
        v = W[((long long)r * 128 + k) * Fout + o];
    } else if (n < Nw_real) {
        v = root[k * Fout + (n - R_REL * Fout)];
    }
    __nv_bfloat16 h = __float2bfloat16(v);
    __nv_bfloat16 l = __float2bfloat16(v - __bfloat162float(h));
    __nv_bfloat16* row = Bout + (long long)n * KTOT;
    row[k] = h; row[128 + k] = h; row[256 + k] = l;
}

// ---------------------------------------------------------------------------
// bf16 tensor-core GEMM (baseline mma.sync + ldmatrix + cp.async):
// C[M,Nw] = A'[M,384] @ B'[Nw,384]^T, fp32 accumulate.
// CTA tile 128x128, K-tile 64, double-buffered. 8 warps: 4(m) x 2(n),
// warp tile 32x64 -> per k16: 2 A-frags x 8 B-frags = 16 mma.
__device__ __forceinline__ void cp16(uint32_t dst, const void* src, int src_sz) {
    asm volatile("cp.async.cg.shared.global [%0], [%1], 16, %2;"
                 :: "r"(dst), "l"(src), "r"(src_sz));
}

__global__ __launch_bounds__(256)
void gemm_bf16_kernel(const __nv_bfloat16* __restrict__ A,
                      const __nv_bfloat16* __restrict__ B,
                      float* __restrict__ C, int M, int Nw) {
    extern __shared__ __align__(1024) char dsm[];
    // layout: sA[2][128*64] bf16 (16KB each), then sB[2][128*64]
    uint32_t sA0 = smem_u32(dsm);
    uint32_t sB0 = sA0 + 2 * BM * BK * 2;

    int tid = threadIdx.x;
    int lane = tid & 31;
    int wid = tid >> 5;
    int warp_m = wid >> 1;     // 0..3
    int warp_n = wid & 1;      // 0..1
    int bm = blockIdx.y * BM;
    int bn = blockIdx.x * BN;

    // gmem->smem mapping: thread covers row = tid>>1, chunks lch0..lch0+3 (16B each)
    int lrow = tid >> 1;
    int lch0 = (tid & 1) * 4;
    int arow_g = bm + lrow;
    int a_ok = (arow_g < M) ? 16 : 0;
    if (arow_g >= M) arow_g = M - 1;             // clamp to keep address valid
    const char* Ag = (const char*)(A + (long long)arow_g * KTOT) + lch0 * 16;
    const char* Bg = (const char*)(B + (long long)(bn + lrow) * KTOT) + lch0 * 16;
    // smem write offsets (swizzled): row*128 + (chunk ^ (row&7))*16
    uint32_t swz_a[4], swz_b[4];
#pragma unroll
    for (int q = 0; q < 4; q++) {
        int ch = lch0 + q;
        swz_a[q] = (uint32_t)lrow * 128u + (uint32_t)((ch ^ (lrow & 7)) * 16);
        swz_b[q] = swz_a[q];
    }

    float acc[2][8][4];
#pragma unroll
    for (int i = 0; i < 2; i++)
#pragma unroll
        for (int j = 0; j < 8; j++)
#pragma unroll
            for (int q = 0; q < 4; q++) acc[i][j][q] = 0.f;

    const int NKT = KTOT / BK;   // 6

    // prefetch tile 0
    {
        uint32_t da = sA0, db = sB0;
#pragma unroll
        for (int q = 0; q < 4; q++) {
            cp16(da + swz_a[q], Ag + q * 16, a_ok);
            cp16(db + swz_b[q], Bg + q * 16, 16);
        }
        asm volatile("cp.async.commit_group;" ::: "memory");
    }

    for (int kt = 0; kt < NKT; kt++) {
        int buf = kt & 1;
        if (kt + 1 < NKT) {
            int nb = (kt + 1) & 1;
            uint32_t da = sA0 + nb * (BM * BK * 2);
            uint32_t db = sB0 + nb * (BN * BK * 2);
            const char* ag = Ag + (long long)(kt + 1) * BK * 2;
            const char* bg = Bg + (long long)(kt + 1) * BK * 2;
#pragma unroll
            for (int q = 0; q < 4; q++) {
                cp16(da + swz_a[q], ag + q * 16, a_ok);
                cp16(db + swz_b[q], bg + q * 16, 16);
            }
            asm volatile("cp.async.commit_group;" ::: "memory");
            asm volatile("cp.async.wait_group 1;" ::: "memory");
        } else {
            asm volatile("cp.async.wait_group 0;" ::: "memory");
        }
        __syncthreads();

        uint32_t abuf = sA0 + buf * (BM * BK * 2);
        uint32_t bbuf = sB0 + buf * (BN * BK * 2);

#pragma unroll
        for (int ks = 0; ks < 4; ks++) {
            // A fragments: two m16 blocks
            uint32_t af[2][4];
#pragma unroll
            for (int mf = 0; mf < 2; mf++) {
                int row = warp_m * 32 + mf * 16 + (lane & 15);
                int ch = ks * 2 + (lane >> 4);
                uint32_t addr = abuf + (uint32_t)row * 128u + (uint32_t)((ch ^ (row & 7)) * 16);
                asm volatile("ldmatrix.sync.aligned.m8n8.x4.shared.b16 {%0,%1,%2,%3}, [%4];"
                             : "=r"(af[mf][0]), "=r"(af[mf][1]), "=r"(af[mf][2]), "=r"(af[mf][3])
                             : "r"(addr));
            }
            // B fragments: 8 n8 blocks, loaded 2 at a time
            uint32_t bf[8][2];
#pragma unroll
            for (int nb = 0; nb < 4; nb++) {
                int n = warp_n * 64 + nb * 16 + ((lane >> 4) * 8) + (lane & 7);
                int ch = ks * 2 + ((lane >> 3) & 1);
                uint32_t addr = bbuf + (uint32_t)n * 128u + (uint32_t)((ch ^ (n & 7)) * 16);
                uint32_t r0, r1, r2, r3;
                asm volatile("ldmatrix.sync.aligned.m8n8.x4.shared.b16 {%0,%1,%2,%3}, [%4];"
                             : "=r"(r0), "=r"(r1), "=r"(r2), "=r"(r3) : "r"(addr));
                bf[nb * 2][0] = r0; bf[nb * 2][1] = r1;
                bf[nb * 2 + 1][0] = r2; bf[nb * 2 + 1][1] = r3;
            }
#pragma unroll
            for (int mf = 0; mf < 2; mf++)
#pragma unroll
                for (int nf = 0; nf < 8; nf++) {
                    asm volatile(
                        "mma.sync.aligned.m16n8k16.row.col.f32.bf16.bf16.f32 "
                        "{%0,%1,%2,%3}, {%4,%5,%6,%7}, {%8,%9}, {%0,%1,%2,%3};"
                        : "+f"(acc[mf][nf][0]), "+f"(acc[mf][nf][1]),
                          "+f"(acc[mf][nf][2]), "+f"(acc[mf][nf][3])
                        : "r"(af[mf][0]), "r"(af[mf][1]), "r"(af[mf][2]), "r"(af[mf][3]),
                          "r"(bf[nf][0]), "r"(bf[nf][1]));
                }
        }
        __syncthreads();
    }

    // Epilogue
    int g = lane >> 2, tg = lane & 3;
#pragma unroll
    for (int mf = 0; mf < 2; mf++) {
        int row0 = bm + warp_m * 32 + mf * 16 + g;
#pragma unroll
        for (int nf = 0; nf < 8; nf++) {
            int col = bn + warp_n * 64 + nf * 8 + tg * 2;
            if (row0 < M)
                *(float2*)(C + (long long)row0 * Nw + col) = make_float2(acc[mf][nf][0], acc[mf][nf][1]);
            if (row0 + 8 < M)
                *(float2*)(C + (long long)(row0 + 8) * Nw + col) = make_float2(acc[mf][nf][2], acc[mf][nf][3]);
        }
    }
}

// ---------------------------------------------------------------------------
// h[n][o] = Y[n][R*Fout + o] + b[o]
__global__ void init_h_kernel(const float* __restrict__ b, float* __restrict__ h,
                              int Fout, int stride) {
    long long i = (long long)blockIdx.x * blockDim.x + threadIdx.x;
    long long total = (long long)N_NODES * Fout;
    if (i < total) {
        int n = (int)(i / Fout), o = (int)(i % Fout);
        h[i] = g_Y[(long long)n * stride + R_REL * Fout + o] + b[o];
    }
}

__global__ __launch_bounds__(256)
void scatter128_kernel(const int* __restrict__ src, const int* __restrict__ dst,
                       const int* __restrict__ etype, float* __restrict__ h) {
    int e = (int)(((long long)blockIdx.x * blockDim.x + threadIdx.x) >> 5);
    int lane = threadIdx.x & 31;
    if (e >= N_EDGES) return;
    int s = src[e], d = dst[e], t = etype[e];
    float wt = g_w[e];
    float4 v = *(const float4*)(g_Y + (long long)s * NW1 + t * 128 + lane * 4);
    v.x *= wt; v.y *= wt; v.z *= wt; v.w *= wt;
    float* out = h + (long long)d * 128 + lane * 4;
    asm volatile("red.global.add.v4.f32 [%0], {%1, %2, %3, %4};"
                 :: "l"(out), "f"(v.x), "f"(v.y), "f"(v.z), "f"(v.w) : "memory");
}

__global__ __launch_bounds__(256)
void scatter64_kernel(const int* __restrict__ src, const int* __restrict__ dst,
                      const int* __restrict__ etype, float* __restrict__ h) {
    int e = (int)(((long long)blockIdx.x * blockDim.x + threadIdx.x) >> 5);
    int lane = threadIdx.x & 31;
    if (e >= N_EDGES) return;
    int s = src[e], d = dst[e], t = etype[e];
    float wt = g_w[e];
    float2 v = *(const float2*)(g_Y + (long long)s * NW2 + t * 64 + lane * 2);
    v.x *= wt; v.y *= wt;
    float* out = h + (long long)d * 64 + lane * 2;
    asm volatile("red.global.add.v2.f32 [%0], {%1, %2};"
                 :: "l"(out), "f"(v.x), "f"(v.y) : "memory");
}

__global__ __launch_bounds__(256)
void classifier_kernel(const float* __restrict__ Wc, const float* __restrict__ bc,
                       float* __restrict__ out) {
    int n = (int)(((long long)blockIdx.x * blockDim.x + threadIdx.x) >> 5);
    int lane = threadIdx.x & 31;
    if (n >= N_NODES) return;
    float a0 = 0.f, a1 = 0.f;
#pragma unroll
    for (int o = lane; o < 64; o += 32) {
        float v = fmaxf(g_h2[(long long)n * 64 + o], 0.f);
        a0 += v * Wc[o * 2 + 0];
        a1 += v * Wc[o * 2 + 1];
    }
#pragma unroll
    for (int off = 16; off; off >>= 1) {
        a0 += __shfl_down_sync(0xffffffffu, a0, off);
        a1 += __shfl_down_sync(0xffffffffu, a1, off);
    }
    if (lane == 0) {
        out[n * 2 + 0] = a0 + bc[0];
        out[n * 2 + 1] = a1 + bc[1];
    }
}

// ---------------------------------------------------------------------------
extern "C" void kernel_launch(void* const* d_in, const int* in_sizes, int n_in,
                              void* d_out, int out_size) {
    const float* x     = (const float*)d_in[0];
    const int*   eidx  = (const int*)d_in[1];
    const int*   etype = (const int*)d_in[2];
    const float* W1    = (const float*)d_in[3];
    const float* root1 = (const float*)d_in[4];
    const float* b1    = (const float*)d_in[5];
    const float* W2    = (const float*)d_in[6];
    const float* root2 = (const float*)d_in[7];
    const float* b2    = (const float*)d_in[8];
    const float* Wc    = (const float*)d_in[9];
    const float* bc    = (const float*)d_in[10];
    float* logits = (float*)d_out;

    const int* src = eidx;
    const int* dst = eidx + N_EDGES;

    float* h1p; cudaGetSymbolAddress((void**)&h1p, g_h1);
    float* h2p; cudaGetSymbolAddress((void**)&h2p, g_h2);
    float* Yp;  cudaGetSymbolAddress((void**)&Yp, g_Y);
    __nv_bfloat16* Ap;  cudaGetSymbolAddress((void**)&Ap, g_A);
    __nv_bfloat16* B1p; cudaGetSymbolAddress((void**)&B1p, g_B1);
    __nv_bfloat16* B2p; cudaGetSymbolAddress((void**)&B2p, g_B2);

    const int GEMM_SMEM = 64 * 1024;   // 2 x (16KB A + 16KB B)
    static int attr_done = 0;
    if (!attr_done) {
        cudaFuncSetAttribute(gemm_bf16_kernel, cudaFuncAttributeMaxDynamicSharedMemorySize, GEMM_SMEM);
        attr_done = 1;
    }

    // Edge preprocessing
    zero_cnt_kernel<<<(R_REL * N_NODES + 255) / 256, 256>>>();
    count_kernel<<<(N_EDGES + 255) / 256, 256>>>(etype, dst);
    weight_kernel<<<(N_EDGES + 255) / 256, 256>>>(etype, dst);

    // Weight conversion (both layers)
    convert_w_kernel<<<(NW1 * 128 + 255) / 256, 256>>>(W1, root1, B1p, F_HID, NW1, NW1);
    convert_w_kernel<<<(NW2 * 128 + 255) / 256, 256>>>(W2, root2, B2p, F_OUT, (R_REL + 1) * F_OUT, NW2);

    long long totA = (long long)N_NODES * 128;

    // ---- Layer 1 ----
    {
        convert_a_kernel<false><<<(int)((totA + 255) / 256), 256>>>(x);
        dim3 grid(NW1 / BN, (N_NODES + BM - 1) / BM);
        gemm_bf16_kernel<<<grid, 256, GEMM_SMEM>>>(Ap, B1p, Yp, N_NODES, NW1);
        init_h_kernel<<<(int)(((long long)N_NODES * F_HID + 255) / 256), 256>>>(b1, h1p, F_HID, NW1);
        scatter128_kernel<<<(N_EDGES * 32 + 255) / 256, 256>>>(src, dst, etype, h1p);
    }

    // ---- Layer 2 (A = relu(h1)) ----
    {
        convert_a_kernel<true><<<(int)((totA + 255) / 256), 256>>>(h1p);
        dim3 grid(NW2 / BN, (N_NODES + BM - 1) / BM);
        gemm_bf16_kernel<<<grid, 256, GEMM_SMEM>>>(Ap, B2p, Yp, N_NODES, NW2);
        init_h_kernel<<<(int)(((long long)N_NODES * F_OUT + 255) / 256), 256>>>(b2, h2p, F_OUT, NW2);
        scatter64_kernel<<<(N_EDGES * 32 + 255) / 256, 256>>>(src, dst, etype, h2p);
    }

    // ---- Classifier ----
    classifier_kernel<<<(N_NODES * 32 + 255) / 256, 256>>>(Wc, bc, logits);
}

// round 4
// speedup vs baseline: 1.7174x; 1.1266x over previous
#include <cuda_runtime.h>
#include <cuda_bf16.h>
#include <cstdint>

// Problem constants
#define N_NODES 50000
#define N_EDGES 640000
#define R_REL   8
#define NW1     1152           // (R+1)*128
#define NW2     640            // (R+1)*64 = 576 padded to 640
#define KTOT    384            // [Ah|Al|Ah] split-bf16 K
#define MT      391            // ceil(50000/128)
#define NBKT    (MT * R_REL)   // 3128

#define BM 128
#define BN 128
#define BK 64

// ---------------------------------------------------------------------------
// Device scratch
__device__ float         g_h1[(long long)N_NODES * 128];
__device__ float         g_h2[(long long)N_NODES * 64];
__device__ int           g_cnt[R_REL * N_NODES];
__device__ __nv_bfloat16 g_A[(long long)N_NODES * KTOT];
__device__ __nv_bfloat16 g_B1[NW1 * KTOT];
__device__ __nv_bfloat16 g_B2[NW2 * KTOT];
__device__ int           g_bkt[NBKT];      // bucket sizes
__device__ int           g_boff[NBKT];     // bucket start offsets
__device__ int           g_bcur[NBKT];     // fill cursors
__device__ uint32_t      g_emeta[N_EDGES]; // dst | (src&127)<<16, bucket-sorted
__device__ float         g_ew[N_EDGES];    // 1/max(cnt,1), bucket-sorted

__device__ __forceinline__ uint32_t smem_u32(const void* p) {
    uint32_t a;
    asm("{ .reg .u64 t; cvta.to.shared.u64 t, %1; cvt.u32.u64 %0, t; }" : "=r"(a) : "l"(p));
    return a;
}
__device__ __forceinline__ void cp16(uint32_t dst, const void* src, int src_sz) {
    asm volatile("cp.async.cg.shared.global [%0], [%1], 16, %2;"
                 :: "r"(dst), "l"(src), "r"(src_sz));
}

// ---------------------------------------------------------------------------
// (0) zero counters
__global__ void zero_kernel() {
    int i = blockIdx.x * blockDim.x + threadIdx.x;
    if (i < R_REL * N_NODES) g_cnt[i] = 0;
    if (i < NBKT) g_bkt[i] = 0;
}

// (1) histogram: per-(type,dst) counts and per-(src-tile,type) bucket counts
__global__ void count_kernel(const int* __restrict__ src, const int* __restrict__ dst,
                             const int* __restrict__ etype) {
    int e = blockIdx.x * blockDim.x + threadIdx.x;
    if (e >= N_EDGES) return;
    int t = etype[e];
    atomicAdd(&g_cnt[t * N_NODES + dst[e]], 1);
    atomicAdd(&g_bkt[(src[e] >> 7) * R_REL + t], 1);
}

// (2) exclusive scan over NBKT buckets (single block, 1024 thr x 4)
__global__ void scan_kernel() {
    __shared__ int tsum[1024];
    int tid = threadIdx.x;
    int base = tid * 4;
    int v[4]; int s = 0;
#pragma unroll
    for (int q = 0; q < 4; q++) {
        v[q] = (base + q < NBKT) ? g_bkt[base + q] : 0;
        s += v[q];
    }
    tsum[tid] = s;
    __syncthreads();
    for (int off = 1; off < 1024; off <<= 1) {
        int t = (tid >= off) ? tsum[tid - off] : 0;
        __syncthreads();
        tsum[tid] += t;
        __syncthreads();
    }
    int ex = tsum[tid] - s;
#pragma unroll
    for (int q = 0; q < 4; q++) {
        if (base + q < NBKT) { g_boff[base + q] = ex; g_bcur[base + q] = ex; }
        ex += v[q];
    }
}

// (3) bucket-sorted edge arrays with per-edge mean weight
__global__ void fill_kernel(const int* __restrict__ src, const int* __restrict__ dst,
                            const int* __restrict__ etype) {
    int e = blockIdx.x * blockDim.x + threadIdx.x;
    if (e >= N_EDGES) return;
    int s = src[e], d = dst[e], t = etype[e];
    int c = g_cnt[t * N_NODES + d];
    int b = (s >> 7) * R_REL + t;
    int pos = atomicAdd(&g_bcur[b], 1);
    g_emeta[pos] = (uint32_t)d | ((uint32_t)(s & 127) << 16);
    g_ew[pos] = 1.0f / (float)(c > 0 ? c : 1);
}

// (4) fused prep: A-split(layer1), W-splits (both layers), bias fills (both h)
#define PREP_A1 6400000LL
#define PREP_W1 147456LL
#define PREP_W2 81920LL
#define PREP_H1 6400000LL
#define PREP_H2 3200000LL
__global__ void prep_kernel(const float* __restrict__ x,
                            const float* __restrict__ W1, const float* __restrict__ root1,
                            const float* __restrict__ b1,
                            const float* __restrict__ W2, const float* __restrict__ root2,
                            const float* __restrict__ b2) {
    long long i = (long long)blockIdx.x * blockDim.x + threadIdx.x;
    if (i < PREP_A1) {
        int n = (int)(i >> 7), j = (int)(i & 127);
        float v = x[i];
        __nv_bfloat16 h = __float2bfloat16(v);
        __nv_bfloat16 l = __float2bfloat16(v - __bfloat162float(h));
        __nv_bfloat16* row = g_A + (long long)n * KTOT;
        row[j] = h; row[128 + j] = l; row[256 + j] = h;
        return;
    }
    i -= PREP_A1;
    if (i < PREP_W1) {
        int n = (int)(i >> 7), k = (int)(i & 127);
        float v;
        if (n < R_REL * 128) {
            int r = n >> 7, o = n & 127;
            v = W1[((long long)r * 128 + k) * 128 + o];
        } else {
            v = root1[k * 128 + (n - R_REL * 128)];
        }
        __nv_bfloat16 h = __float2bfloat16(v);
        __nv_bfloat16 l = __float2bfloat16(v - __bfloat162float(h));
        __nv_bfloat16* row = g_B1 + (long long)n * KTOT;
        row[k] = h; row[128 + k] = h; row[256 + k] = l;
        return;
    }
    i -= PREP_W1;
    if (i < PREP_W2) {
        int n = (int)(i >> 7), k = (int)(i & 127);
        float v = 0.f;
        if (n < R_REL * 64) {
            int r = n >> 6, o = n & 63;
            v = W2[((long long)r * 128 + k) * 64 + o];
        } else if (n < 576) {
            v = root2[k * 64 + (n - R_REL * 64)];
        }
        __nv_bfloat16 h = __float2bfloat16(v);
        __nv_bfloat16 l = __float2bfloat16(v - __bfloat162float(h));
        __nv_bfloat16* row = g_B2 + (long long)n * KTOT;
        row[k] = h; row[128 + k] = h; row[256 + k] = l;
        return;
    }
    i -= PREP_W2;
    if (i < PREP_H1) { g_h1[i] = b1[(int)(i & 127)]; return; }
    i -= PREP_H1;
    if (i < PREP_H2) { g_h2[i] = b2[(int)(i & 63)]; }
}

// (6) A-split for layer 2 (relu applied)
__global__ void convert_a2_kernel(const float* __restrict__ H) {
    long long i = (long long)blockIdx.x * blockDim.x + threadIdx.x;
    if (i >= (long long)N_NODES * 128) return;
    int n = (int)(i >> 7), j = (int)(i & 127);
    float v = fmaxf(H[i], 0.f);
    __nv_bfloat16 h = __float2bfloat16(v);
    __nv_bfloat16 l = __float2bfloat16(v - __bfloat162float(h));
    __nv_bfloat16* row = g_A + (long long)n * KTOT;
    row[j] = h; row[128 + j] = l; row[256 + j] = h;
}

// ---------------------------------------------------------------------------
// Fused GEMM + scatter. FH = 128 (layer1) or 64 (layer2).
// Tile 128x128, K=384 in 6 steps of 64, 3-stage cp.async pipeline.
// Relation tiles: stage result in smem, replay bucket edges with red.add into h.
// Root tiles: red.add accumulators directly into h.
template <int FH>
__global__ __launch_bounds__(256)
void gemm_fused_kernel(const __nv_bfloat16* __restrict__ A,
                       const __nv_bfloat16* __restrict__ B,
                       float* __restrict__ H, int M) {
    extern __shared__ __align__(1024) char dsm[];
    const uint32_t sA0 = smem_u32(dsm);
    const uint32_t sB0 = sA0 + 3 * BM * BK * 2;

    int tid = threadIdx.x;
    int lane = tid & 31;
    int wid = tid >> 5;
    int warp_m = wid >> 1;
    int warp_n = wid & 1;
    int bm = blockIdx.y * BM;
    int bn = blockIdx.x * BN;

    // gmem->smem: thread covers row tid>>1, 4 x 16B chunks
    int lrow = tid >> 1;
    int lch0 = (tid & 1) * 4;
    int arow_g = bm + lrow;
    int a_ok = (arow_g < M) ? 16 : 0;
    if (arow_g >= M) arow_g = M - 1;
    const char* Ag = (const char*)(A + (long long)arow_g * KTOT) + lch0 * 16;
    const char* Bg = (const char*)(B + (long long)(bn + lrow) * KTOT) + lch0 * 16;
    uint32_t swz[4];
#pragma unroll
    for (int q = 0; q < 4; q++) {
        int ch = lch0 + q;
        swz[q] = (uint32_t)lrow * 128u + (uint32_t)((ch ^ (lrow & 7)) * 16);
    }

    float acc[2][8][4];
#pragma unroll
    for (int i = 0; i < 2; i++)
#pragma unroll
        for (int j = 0; j < 8; j++)
#pragma unroll
            for (int q = 0; q < 4; q++) acc[i][j][q] = 0.f;

    const int NKT = KTOT / BK;   // 6

    // prefetch stages 0 and 1
#pragma unroll
    for (int st = 0; st < 2; st++) {
        uint32_t da = sA0 + st * (BM * BK * 2);
        uint32_t db = sB0 + st * (BN * BK * 2);
        const char* ag = Ag + (long long)st * BK * 2;
        const char* bg = Bg + (long long)st * BK * 2;
#pragma unroll
        for (int q = 0; q < 4; q++) {
            cp16(da + swz[q], ag + q * 16, a_ok);
            cp16(db + swz[q], bg + q * 16, 16);
        }
        asm volatile("cp.async.commit_group;" ::: "memory");
    }

    for (int kt = 0; kt < NKT; kt++) {
        if (kt + 2 < NKT) {
            asm volatile("cp.async.wait_group 1;" ::: "memory");
        } else {
            asm volatile("cp.async.wait_group 0;" ::: "memory");
        }
        __syncthreads();
        if (kt + 2 < NKT) {
            int slot = (kt + 2) % 3;
            uint32_t da = sA0 + slot * (BM * BK * 2);
            uint32_t db = sB0 + slot * (BN * BK * 2);
            const char* ag = Ag + (long long)(kt + 2) * BK * 2;
            const char* bg = Bg + (long long)(kt + 2) * BK * 2;
#pragma unroll
            for (int q = 0; q < 4; q++) {
                cp16(da + swz[q], ag + q * 16, a_ok);
                cp16(db + swz[q], bg + q * 16, 16);
            }
            asm volatile("cp.async.commit_group;" ::: "memory");
        }

        int buf = kt % 3;
        uint32_t abuf = sA0 + buf * (BM * BK * 2);
        uint32_t bbuf = sB0 + buf * (BN * BK * 2);

#pragma unroll
        for (int ks = 0; ks < 4; ks++) {
            uint32_t af[2][4];
#pragma unroll
            for (int mf = 0; mf < 2; mf++) {
                int row = warp_m * 32 + mf * 16 + (lane & 15);
                int ch = ks * 2 + (lane >> 4);
                uint32_t addr = abuf + (uint32_t)row * 128u + (uint32_t)((ch ^ (row & 7)) * 16);
                asm volatile("ldmatrix.sync.aligned.m8n8.x4.shared.b16 {%0,%1,%2,%3}, [%4];"
                             : "=r"(af[mf][0]), "=r"(af[mf][1]), "=r"(af[mf][2]), "=r"(af[mf][3])
                             : "r"(addr));
            }
            uint32_t bfr[8][2];
#pragma unroll
            for (int nb = 0; nb < 4; nb++) {
                int n = warp_n * 64 + nb * 16 + ((lane >> 4) * 8) + (lane & 7);
                int ch = ks * 2 + ((lane >> 3) & 1);
                uint32_t addr = bbuf + (uint32_t)n * 128u + (uint32_t)((ch ^ (n & 7)) * 16);
                uint32_t r0, r1, r2, r3;
                asm volatile("ldmatrix.sync.aligned.m8n8.x4.shared.b16 {%0,%1,%2,%3}, [%4];"
                             : "=r"(r0), "=r"(r1), "=r"(r2), "=r"(r3) : "r"(addr));
                bfr[nb * 2][0] = r0;     bfr[nb * 2][1] = r1;
                bfr[nb * 2 + 1][0] = r2; bfr[nb * 2 + 1][1] = r3;
            }
#pragma unroll
            for (int mf = 0; mf < 2; mf++)
#pragma unroll
                for (int nf = 0; nf < 8; nf++) {
                    asm volatile(
                        "mma.sync.aligned.m16n8k16.row.col.f32.bf16.bf16.f32 "
                        "{%0,%1,%2,%3}, {%4,%5,%6,%7}, {%8,%9}, {%0,%1,%2,%3};"
                        : "+f"(acc[mf][nf][0]), "+f"(acc[mf][nf][1]),
                          "+f"(acc[mf][nf][2]), "+f"(acc[mf][nf][3])
                        : "r"(af[mf][0]), "r"(af[mf][1]), "r"(af[mf][2]), "r"(af[mf][3]),
                          "r"(bfr[nf][0]), "r"(bfr[nf][1]));
                }
        }
        __syncthreads();
    }

    int g = lane >> 2, tg = lane & 3;
    const bool is_root = (FH == 128) ? (blockIdx.x == 8) : (blockIdx.x == 4);

    if (is_root) {
        // direct red of accumulators into H (root term)
        if (FH == 64 && warp_n == 1) return;   // pad half
#pragma unroll
        for (int mf = 0; mf < 2; mf++) {
            int row0 = bm + warp_m * 32 + mf * 16 + g;
#pragma unroll
            for (int nf = 0; nf < 8; nf++) {
                int colh = ((FH == 128) ? warp_n * 64 : 0) + nf * 8 + tg * 2;
                if (row0 < M)
                    asm volatile("red.global.add.v2.f32 [%0], {%1, %2};"
                                 :: "l"(H + (long long)row0 * FH + colh),
                                    "f"(acc[mf][nf][0]), "f"(acc[mf][nf][1]) : "memory");
                if (row0 + 8 < M)
                    asm volatile("red.global.add.v2.f32 [%0], {%1, %2};"
                                 :: "l"(H + (long long)(row0 + 8) * FH + colh),
                                    "f"(acc[mf][nf][2]), "f"(acc[mf][nf][3]) : "memory");
            }
        }
        return;
    }

    // stage result tile into smem (128 x 128 f32 = 64KB, fits in 96KB)
    float* stg = (float*)dsm;
#pragma unroll
    for (int mf = 0; mf < 2; mf++) {
        int r0 = warp_m * 32 + mf * 16 + g;
#pragma unroll
        for (int nf = 0; nf < 8; nf++) {
            int c = warp_n * 64 + nf * 8 + tg * 2;
            *(float2*)(stg + r0 * 128 + c)       = make_float2(acc[mf][nf][0], acc[mf][nf][1]);
            *(float2*)(stg + (r0 + 8) * 128 + c) = make_float2(acc[mf][nf][2], acc[mf][nf][3]);
        }
    }
    __syncthreads();

    // scatter bucket edges
    if (FH == 128) {
        int b = blockIdx.y * R_REL + blockIdx.x;
        int s0 = g_boff[b], cnt = g_bkt[b];
        for (int i = wid; i < cnt; i += 8) {
            uint32_t m = g_emeta[s0 + i];
            float w = g_ew[s0 + i];
            int sl = (int)(m >> 16);
            int d = (int)(m & 0xFFFFu);
            float4 v = *(const float4*)(stg + sl * 128 + lane * 4);
            v.x *= w; v.y *= w; v.z *= w; v.w *= w;
            asm volatile("red.global.add.v4.f32 [%0], {%1, %2, %3, %4};"
                         :: "l"(H + (long long)d * 128 + lane * 4),
                            "f"(v.x), "f"(v.y), "f"(v.z), "f"(v.w) : "memory");
        }
    } else {
        int half = wid >> 2;                 // which 64-col half => relation
        int b = blockIdx.y * R_REL + blockIdx.x * 2 + half;
        int s0 = g_boff[b], cnt = g_bkt[b];
        for (int i = (wid & 3); i < cnt; i += 4) {
            uint32_t m = g_emeta[s0 + i];
            float w = g_ew[s0 + i];
            int sl = (int)(m >> 16);
            int d = (int)(m & 0xFFFFu);
            float2 v = *(const float2*)(stg + sl * 128 + half * 64 + lane * 2);
            v.x *= w; v.y *= w;
            asm volatile("red.global.add.v2.f32 [%0], {%1, %2};"
                         :: "l"(H + (long long)d * 64 + lane * 2),
                            "f"(v.x), "f"(v.y) : "memory");
        }
    }
}

// ---------------------------------------------------------------------------
__global__ __launch_bounds__(256)
void classifier_kernel(const float* __restrict__ Wc, const float* __restrict__ bc,
                       float* __restrict__ out) {
    int n = (int)(((long long)blockIdx.x * blockDim.x + threadIdx.x) >> 5);
    int lane = threadIdx.x & 31;
    if (n >= N_NODES) return;
    float a0 = 0.f, a1 = 0.f;
#pragma unroll
    for (int o = lane; o < 64; o += 32) {
        float v = fmaxf(g_h2[(long long)n * 64 + o], 0.f);
        a0 += v * Wc[o * 2 + 0];
        a1 += v * Wc[o * 2 + 1];
    }
#pragma unroll
    for (int off = 16; off; off >>= 1) {
        a0 += __shfl_down_sync(0xffffffffu, a0, off);
        a1 += __shfl_down_sync(0xffffffffu, a1, off);
    }
    if (lane == 0) {
        out[n * 2 + 0] = a0 + bc[0];
        out[n * 2 + 1] = a1 + bc[1];
    }
}

// ---------------------------------------------------------------------------
extern "C" void kernel_launch(void* const* d_in, const int* in_sizes, int n_in,
                              void* d_out, int out_size) {
    const float* x     = (const float*)d_in[0];
    const int*   eidx  = (const int*)d_in[1];
    const int*   etype = (const int*)d_in[2];
    const float* W1    = (const float*)d_in[3];
    const float* root1 = (const float*)d_in[4];
    const float* b1    = (const float*)d_in[5];
    const float* W2    = (const float*)d_in[6];
    const float* root2 = (const float*)d_in[7];
    const float* b2    = (const float*)d_in[8];
    const float* Wc    = (const float*)d_in[9];
    const float* bc    = (const float*)d_in[10];
    float* logits = (float*)d_out;

    const int* src = eidx;
    const int* dst = eidx + N_EDGES;

    float* h1p; cudaGetSymbolAddress((void**)&h1p, g_h1);
    float* h2p; cudaGetSymbolAddress((void**)&h2p, g_h2);
    __nv_bfloat16* Ap;  cudaGetSymbolAddress((void**)&Ap, g_A);
    __nv_bfloat16* B1p; cudaGetSymbolAddress((void**)&B1p, g_B1);
    __nv_bfloat16* B2p; cudaGetSymbolAddress((void**)&B2p, g_B2);

    const int GEMM_SMEM = 3 * 2 * BM * BK * 2;   // 96KB
    static int attr_done = 0;
    if (!attr_done) {
        cudaFuncSetAttribute(gemm_fused_kernel<128>, cudaFuncAttributeMaxDynamicSharedMemorySize, GEMM_SMEM);
        cudaFuncSetAttribute(gemm_fused_kernel<64>,  cudaFuncAttributeMaxDynamicSharedMemorySize, GEMM_SMEM);
        attr_done = 1;
    }

    // 0: zero counters
    zero_kernel<<<(R_REL * N_NODES + 255) / 256, 256>>>();
    // 1: histograms
    count_kernel<<<N_EDGES / 256, 256>>>(src, dst, etype);
    // 2: bucket scan
    scan_kernel<<<1, 1024>>>();
    // 3: bucket-sorted edge arrays
    fill_kernel<<<N_EDGES / 256, 256>>>(src, dst, etype);
    // 4: fused prep (A-split, W-splits, bias fills)
    {
        long long total = PREP_A1 + PREP_W1 + PREP_W2 + PREP_H1 + PREP_H2;
        prep_kernel<<<(int)((total + 255) / 256), 256>>>(x, W1, root1, b1, W2, root2, b2);
    }
    // 5: layer-1 fused GEMM+scatter  (profiled launch)
    {
        dim3 grid(NW1 / BN, (N_NODES + BM - 1) / BM);
        gemm_fused_kernel<128><<<grid, 256, GEMM_SMEM>>>(Ap, B1p, h1p, N_NODES);
    }
    // 6: layer-2 A split (relu)
    convert_a2_kernel<<<(int)(((long long)N_NODES * 128 + 255) / 256), 256>>>(h1p);
    // 7: layer-2 fused GEMM+scatter
    {
        dim3 grid(NW2 / BN, (N_NODES + BM - 1) / BM);
        gemm_fused_kernel<64><<<grid, 256, GEMM_SMEM>>>(Ap, B2p, h2p, N_NODES);
    }
    // 8: classifier
    classifier_kernel<<<(int)(((long long)N_NODES * 32 + 255) / 256), 256>>>(Wc, bc, logits);
}